// round 1
// baseline (speedup 1.0000x reference)
#include <cuda_runtime.h>
#include <math.h>
#include <stdint.h>

#define NNODES 100000
#define NEDGES 1600000
#define FDIN   256
#define FH     256
#define FOUT   64

// ---------------- scratch (device globals; no runtime allocation) ----------------
__device__ float g_buf0[(size_t)NNODES * 256];
__device__ float g_buf1[(size_t)NNODES * 256];
__device__ float g_buf2[(size_t)NNODES * 256];
__device__ float g_buf3[(size_t)NNODES * 256];

__device__ int   g_rowptrA[NNODES + 1];
__device__ int   g_colA[NEDGES];
__device__ float g_valA[NEDGES];
__device__ int   g_rowptrL[NNODES + 1];
__device__ int   g_colL[NEDGES];
__device__ float g_valL[NEDGES];
__device__ int   g_cnt[NNODES];
__device__ int   g_cur[NNODES];

// ---------------- small utility kernels ----------------
__global__ void k_zero_int(int* p, int n) {
    int i = blockIdx.x * blockDim.x + threadIdx.x;
    if (i < n) p[i] = 0;
}

__global__ void k_count(const int* __restrict__ rows, int* __restrict__ cnt, int E) {
    int e = blockIdx.x * blockDim.x + threadIdx.x;
    if (e < E) atomicAdd(&cnt[rows[e]], 1);
}

// single-block chunked inclusive scan -> exclusive rowptr
__global__ void k_scan(const int* __restrict__ cnt, int* __restrict__ rowptr, int n) {
    __shared__ int sh[1024];
    __shared__ int carry;
    int tid = threadIdx.x;
    if (tid == 0) carry = 0;
    __syncthreads();
    for (int base = 0; base < n; base += 1024) {
        int i = base + tid;
        int v = (i < n) ? cnt[i] : 0;
        sh[tid] = v;
        __syncthreads();
        for (int off = 1; off < 1024; off <<= 1) {
            int t = (tid >= off) ? sh[tid - off] : 0;
            __syncthreads();
            sh[tid] += t;
            __syncthreads();
        }
        if (i < n) rowptr[i + 1] = carry + sh[tid];
        __syncthreads();
        if (tid == 0) carry += sh[1023];
        __syncthreads();
    }
    if (tid == 0) rowptr[0] = 0;
}

__global__ void k_scatter(const int* __restrict__ rows, const int* __restrict__ cols,
                          const float* __restrict__ vals,
                          const int* __restrict__ rowptr, int* __restrict__ cur,
                          int* __restrict__ colO, float* __restrict__ valO, int E) {
    int e = blockIdx.x * blockDim.x + threadIdx.x;
    if (e >= E) return;
    int r = rows[e];
    int p = rowptr[r] + atomicAdd(&cur[r], 1);
    colO[p] = cols[e];
    valO[p] = vals[e];
}

// ---------------- activations ----------------
__device__ __forceinline__ float actf(float x) {
    // w1*soft(0.1) - w2*soft(0.5), w1=1.8, w2=0.8
    float s1 = fmaxf(x - 0.1f, 0.f) - fmaxf(-x - 0.1f, 0.f);
    float s2 = fmaxf(x - 0.5f, 0.f) - fmaxf(-x - 0.5f, 0.f);
    return 1.8f * s1 - 0.8f * s2;
}

// ---------------- CSR SpMM (row-parallel, float4 lanes) ----------------
// out[row,f] = relu(sum_e val*X[col,f] + bias[f])
template <int F4>
__global__ void k_spmm_relu(const int* __restrict__ rowptr, const int* __restrict__ col,
                            const float* __restrict__ val, const float* __restrict__ X,
                            const float* __restrict__ bias, float* __restrict__ out) {
    int t = blockIdx.x * blockDim.x + threadIdx.x;
    int row = t / F4;
    int f = t % F4;
    if (row >= NNODES) return;
    int s = rowptr[row], e = rowptr[row + 1];
    const float4* X4 = (const float4*)X;
    float4 acc = make_float4(0.f, 0.f, 0.f, 0.f);
    for (int p = s; p < e; p++) {
        int c = __ldg(&col[p]);
        float v = __ldg(&val[p]);
        float4 xv = X4[(size_t)c * F4 + f];
        acc.x = fmaf(v, xv.x, acc.x);
        acc.y = fmaf(v, xv.y, acc.y);
        acc.z = fmaf(v, xv.z, acc.z);
        acc.w = fmaf(v, xv.w, acc.w);
    }
    float4 b = ((const float4*)bias)[f];
    float4 o;
    o.x = fmaxf(acc.x + b.x, 0.f);
    o.y = fmaxf(acc.y + b.y, 0.f);
    o.z = fmaxf(acc.z + b.z, 0.f);
    o.w = fmaxf(acc.w + b.w, 0.f);
    ((float4*)out)[(size_t)row * F4 + f] = o;
}

// out[row,f] = act(T[row,f] - lamda * sum_e val*X[col,f]),  lamda = 1
template <int F4>
__global__ void k_spmm_embed(const int* __restrict__ rowptr, const int* __restrict__ col,
                             const float* __restrict__ val, const float* __restrict__ X,
                             const float* __restrict__ T, float* __restrict__ out) {
    int t = blockIdx.x * blockDim.x + threadIdx.x;
    int row = t / F4;
    int f = t % F4;
    if (row >= NNODES) return;
    int s = rowptr[row], e = rowptr[row + 1];
    const float4* X4 = (const float4*)X;
    float4 acc = make_float4(0.f, 0.f, 0.f, 0.f);
    for (int p = s; p < e; p++) {
        int c = __ldg(&col[p]);
        float v = __ldg(&val[p]);
        float4 xv = X4[(size_t)c * F4 + f];
        acc.x = fmaf(v, xv.x, acc.x);
        acc.y = fmaf(v, xv.y, acc.y);
        acc.z = fmaf(v, xv.z, acc.z);
        acc.w = fmaf(v, xv.w, acc.w);
    }
    float4 tv = ((const float4*)T)[(size_t)row * F4 + f];
    float4 o;
    o.x = actf(tv.x - acc.x);
    o.y = actf(tv.y - acc.y);
    o.z = actf(tv.z - acc.z);
    o.w = actf(tv.w - acc.w);
    ((float4*)out)[(size_t)row * F4 + f] = o;
}

// ---------------- tiled fp32 GEMM ----------------
// C[M,Nc] = A[M,K] @ B[K,Nc]  (+C if accFlag) (+bias) (tanh if actFlag)
// BM=128, BN=64, BK=8, 256 threads, per-thread 8x4. K % 8 == 0, Nc % 64 == 0.
__global__ __launch_bounds__(256) void k_gemm(const float* __restrict__ A,
                                              const float* __restrict__ B,
                                              float* __restrict__ C,
                                              int M, int K, int Nc,
                                              const float* __restrict__ bias,
                                              int accFlag, int actFlag) {
    const int BM = 128, BN = 64, BK = 8, TM = 8, TN = 4;
    __shared__ float As[BK][BM];
    __shared__ float Bs[BK][BN];
    int tid = threadIdx.x;
    int bm = blockIdx.x * BM;
    int bn = blockIdx.y * BN;
    int tx = tid & 15;       // 0..15 (cols)
    int ty = tid >> 4;       // 0..15 (rows)
    int ar = tid >> 1;       // 0..127 A row in tile
    int ac = tid & 1;        // which float4 of the BK=8 cols

    float acc[TM][TN];
#pragma unroll
    for (int i = 0; i < TM; i++)
#pragma unroll
        for (int j = 0; j < TN; j++) acc[i][j] = 0.f;

    for (int k0 = 0; k0 < K; k0 += BK) {
        // load A tile (128 x 8), transposed into As[k][m]
        float4 av = make_float4(0.f, 0.f, 0.f, 0.f);
        int arow = bm + ar;
        if (arow < M) av = *(const float4*)(A + (size_t)arow * K + k0 + ac * 4);
        As[ac * 4 + 0][ar] = av.x;
        As[ac * 4 + 1][ar] = av.y;
        As[ac * 4 + 2][ar] = av.z;
        As[ac * 4 + 3][ar] = av.w;
        // load B tile (8 x 64)
        if (tid < 128) {
            int brr = tid >> 4;  // 0..7
            int bcc = tid & 15;  // 0..15
            float4 bv = *(const float4*)(B + (size_t)(k0 + brr) * Nc + bn + bcc * 4);
            *(float4*)&Bs[brr][bcc * 4] = bv;
        }
        __syncthreads();
#pragma unroll
        for (int k = 0; k < BK; k++) {
            float ra[TM];
#pragma unroll
            for (int i = 0; i < TM; i++) ra[i] = As[k][ty * TM + i];
            float4 rb4 = *(float4*)&Bs[k][tx * TN];
            float rb[TN] = {rb4.x, rb4.y, rb4.z, rb4.w};
#pragma unroll
            for (int i = 0; i < TM; i++)
#pragma unroll
                for (int j = 0; j < TN; j++) acc[i][j] = fmaf(ra[i], rb[j], acc[i][j]);
        }
        __syncthreads();
    }

    float4 bv = make_float4(0.f, 0.f, 0.f, 0.f);
    if (bias) bv = *(const float4*)(bias + bn + tx * TN);
#pragma unroll
    for (int i = 0; i < TM; i++) {
        int row = bm + ty * TM + i;
        if (row >= M) continue;
        size_t off = (size_t)row * Nc + bn + tx * TN;
        float4 c = make_float4(acc[i][0], acc[i][1], acc[i][2], acc[i][3]);
        if (accFlag) {
            float4 o = *(float4*)(C + off);
            c.x += o.x; c.y += o.y; c.z += o.z; c.w += o.w;
        }
        c.x += bv.x; c.y += bv.y; c.z += bv.z; c.w += bv.w;
        if (actFlag) {
            c.x = tanhf(c.x); c.y = tanhf(c.y); c.z = tanhf(c.z); c.w = tanhf(c.w);
        }
        *(float4*)(C + off) = c;
    }
}

// ---------------- host orchestration ----------------
static inline void gemm(const float* A, const float* B, float* C, int M, int K, int Nc,
                        const float* bias, int accFlag, int actFlag) {
    dim3 grid((M + 127) / 128, Nc / 64);
    k_gemm<<<grid, 256>>>(A, B, C, M, K, Nc, bias, accFlag, actFlag);
}

extern "C" void kernel_launch(void* const* d_in, const int* in_sizes, int n_in,
                              void* d_out, int out_size) {
    (void)in_sizes; (void)n_in; (void)out_size;
    const float* x      = (const float*)d_in[0];
    const int*   A_idx  = (const int*)d_in[1];   // [2, E]: rows then cols
    const float* A_val  = (const float*)d_in[2];
    const int*   L_idx  = (const int*)d_in[3];
    const float* L_val  = (const float*)d_in[4];
    const float* gcn_w0 = (const float*)d_in[5];
    const float* gcn_b0 = (const float*)d_in[6];
    const float* pai1_0 = (const float*)d_in[7];
    const float* pai2_0 = (const float*)d_in[8];
    const float* w1_w0  = (const float*)d_in[9];
    const float* w1_b0  = (const float*)d_in[10];
    const float* w2_w0  = (const float*)d_in[11];
    const float* w2_b0  = (const float*)d_in[12];
    const float* gcn_w1 = (const float*)d_in[13];
    const float* gcn_b1 = (const float*)d_in[14];
    const float* pai1_1 = (const float*)d_in[15];
    const float* pai2_1 = (const float*)d_in[16];
    const float* w1_w1  = (const float*)d_in[17];
    const float* w1_b1  = (const float*)d_in[18];
    const float* w2_w1  = (const float*)d_in[19];
    const float* w2_b1  = (const float*)d_in[20];

    float* out = (float*)d_out;
    float* out_ztp0 = out;                               // z_tp_list[0]
    float* out_ztp1 = out + (size_t)NNODES * FOUT;       // z_tp_list[1]
    float* out_zem0 = out + (size_t)2 * NNODES * FOUT;   // z_embed_list[0]
    float* out_zem1 = out + (size_t)3 * NNODES * FOUT;   // z_embed_list[1]

    float *buf0, *buf1, *buf2, *buf3, *valA, *valL;
    int *rowptrA, *colA, *rowptrL, *colL, *cnt, *cur;
    cudaGetSymbolAddress((void**)&buf0, g_buf0);
    cudaGetSymbolAddress((void**)&buf1, g_buf1);
    cudaGetSymbolAddress((void**)&buf2, g_buf2);
    cudaGetSymbolAddress((void**)&buf3, g_buf3);
    cudaGetSymbolAddress((void**)&rowptrA, g_rowptrA);
    cudaGetSymbolAddress((void**)&colA, g_colA);
    cudaGetSymbolAddress((void**)&valA, g_valA);
    cudaGetSymbolAddress((void**)&rowptrL, g_rowptrL);
    cudaGetSymbolAddress((void**)&colL, g_colL);
    cudaGetSymbolAddress((void**)&valL, g_valL);
    cudaGetSymbolAddress((void**)&cnt, g_cnt);
    cudaGetSymbolAddress((void**)&cur, g_cur);

    const int TB = 256;
    int gbN = (NNODES + TB - 1) / TB;
    int gbE = (NEDGES + TB - 1) / TB;

    // ---- build CSR for A ----
    k_zero_int<<<gbN, TB>>>(cnt, NNODES);
    k_zero_int<<<gbN, TB>>>(cur, NNODES);
    k_count<<<gbE, TB>>>(A_idx, cnt, NEDGES);
    k_scan<<<1, 1024>>>(cnt, rowptrA, NNODES);
    k_scatter<<<gbE, TB>>>(A_idx, A_idx + NEDGES, A_val, rowptrA, cur, colA, valA, NEDGES);
    // ---- build CSR for L ----
    k_zero_int<<<gbN, TB>>>(cnt, NNODES);
    k_zero_int<<<gbN, TB>>>(cur, NNODES);
    k_count<<<gbE, TB>>>(L_idx, cnt, NEDGES);
    k_scan<<<1, 1024>>>(cnt, rowptrL, NNODES);
    k_scatter<<<gbE, TB>>>(L_idx, L_idx + NEDGES, L_val, rowptrL, cur, colL, valL, NEDGES);

    // ================= layer 0 (din=256 -> h=256) =================
    // 1) buf0 = x @ gcn_w0
    gemm(x, gcn_w0, buf0, NNODES, FDIN, FH, nullptr, 0, 0);
    // 2) buf1 = relu(A @ buf0 + gcn_b0)   (Z_tp0)
    {
        int threads = NNODES * (FH / 4);
        k_spmm_relu<FH / 4><<<(threads + TB - 1) / TB, TB>>>(rowptrA, colA, valA, buf0, gcn_b0, buf1);
    }
    // 3) out_ztp0 = tanh(buf1 @ w1_w0 + w1_b0)
    gemm(buf1, w1_w0, out_ztp0, NNODES, FH, FOUT, w1_b0, 0, 1);
    // 4) buf2 = buf1 @ pai1_0 + x @ pai2_0
    gemm(buf1, pai1_0, buf2, NNODES, FH, FH, nullptr, 0, 0);
    gemm(x, pai2_0, buf2, NNODES, FDIN, FH, nullptr, 1, 0);
    // 5) buf3 = act(buf2 - L @ buf1)   (Z_embed0)
    {
        int threads = NNODES * (FH / 4);
        k_spmm_embed<FH / 4><<<(threads + TB - 1) / TB, TB>>>(rowptrL, colL, valL, buf1, buf2, buf3);
    }
    // 6) out_zem0 = tanh(buf3 @ w2_w0 + w2_b0)
    gemm(buf3, w2_w0, out_zem0, NNODES, FH, FOUT, w2_b0, 0, 1);

    // ================= layer 1 (h=256 -> dout=64) =================
    // 7) buf0 = buf3 @ gcn_w1   (N x 64)
    gemm(buf3, gcn_w1, buf0, NNODES, FH, FOUT, nullptr, 0, 0);
    // 8) buf1 = relu(A @ buf0 + gcn_b1)   (Z_tp1, N x 64)
    {
        int threads = NNODES * (FOUT / 4);
        k_spmm_relu<FOUT / 4><<<(threads + TB - 1) / TB, TB>>>(rowptrA, colA, valA, buf0, gcn_b1, buf1);
    }
    // 9) out_ztp1 = tanh(buf1 @ w1_w1 + w1_b1)
    gemm(buf1, w1_w1, out_ztp1, NNODES, FOUT, FOUT, w1_b1, 0, 1);
    // 10) buf2 = buf1 @ pai1_1 + x @ pai2_1   (N x 64)
    gemm(buf1, pai1_1, buf2, NNODES, FOUT, FOUT, nullptr, 0, 0);
    gemm(x, pai2_1, buf2, NNODES, FDIN, FOUT, nullptr, 1, 0);
    // 11) buf3 = act(buf2 - L @ buf1)   (Z_embed1, N x 64)
    {
        int threads = NNODES * (FOUT / 4);
        k_spmm_embed<FOUT / 4><<<(threads + TB - 1) / TB, TB>>>(rowptrL, colL, valL, buf1, buf2, buf3);
    }
    // 12) out_zem1 = tanh(buf3 @ w2_w1 + w2_b1)
    gemm(buf3, w2_w1, out_zem1, NNODES, FOUT, FOUT, w2_b1, 0, 1);
}